// round 17
// baseline (speedup 1.0000x reference)
#include <cuda_runtime.h>

// Batched Kalman step: B=131072, STATE=16, OBS=8 — TWO-KERNEL SPLIT.
// Kernel A (update): 4 lanes/batch -> NC (new covariance) + new_mean to
//   __device__ scratch. No phase 7/8 => register peak ~110, 4 blocks/SM.
// Kernel B (predict): 8 lanes/batch, pure streaming: pcov = F*NC*F^T + Q,
//   pmean = F*new_mean. No Cholesky chain, high MLP, DRAM-bound.

using ull = unsigned long long;
using u2  = ulonglong2;

__device__ __forceinline__ ull pk2(float lo, float hi) {
    ull r; asm("mov.b64 %0, {%1,%2};" : "=l"(r) : "f"(lo), "f"(hi)); return r;
}
__device__ __forceinline__ ull pk1(float x) {
    ull r; asm("mov.b64 %0, {%1,%1};" : "=l"(r) : "f"(x)); return r;
}
__device__ __forceinline__ void upk(ull v, float& lo, float& hi) {
    asm("mov.b64 {%0,%1}, %2;" : "=f"(lo), "=f"(hi) : "l"(v));
}
__device__ __forceinline__ ull ffma2(ull a, ull b, ull c) {
    ull d; asm("fma.rn.f32x2 %0, %1, %2, %3;" : "=l"(d) : "l"(a), "l"(b), "l"(c)); return d;
}
__device__ __forceinline__ ull add2(ull a, ull b) {
    ull d; asm("add.rn.f32x2 %0, %1, %2;" : "=l"(d) : "l"(a), "l"(b)); return d;
}
__device__ __forceinline__ float hsum(ull a) {
    float lo, hi; upk(a, lo, hi); return lo + hi;
}

static constexpr int NB_MAX = 131072;
__device__ float g_nc[NB_MAX * 256];   // new_cov scratch (134MB, module-static)
__device__ float g_nm[NB_MAX * 16];    // new_mean scratch (8MB)

// ============================ Kernel A: update ============================
static constexpr int GA  = 32;       // batches per block
static constexpr int TPA = 128;      // 4 lanes per batch
static constexpr int ASB   = 292;    // per-batch smem floats; ≡4 mod 32 banks
static constexpr int AXO   = 0;      // 16x16: HT -> WT(rows0-7)/SS
static constexpr int AWT   = 0;
static constexpr int ASS   = 128;
static constexpr int ASM   = 256;    // mean[16]
static constexpr int ASR   = 272;    // resid[8]

__global__ void __launch_bounds__(TPA, 4) kf_update(
    const float* __restrict__ gin,  const float* __restrict__ gmean,
    const float* __restrict__ gcov, const float* __restrict__ gH,
    const float* __restrict__ gR,   int nb)
{
    __shared__ __align__(16) float sm[GA * ASB];
    const int g = threadIdx.x >> 2;
    const int t = threadIdx.x & 3;
    long long b = (long long)blockIdx.x * GA + g;
    const bool valid = (b < nb);
    if (!valid) b = nb - 1;
    float* S = sm + g * ASB;

    int rr[4];
#pragma unroll
    for (int k = 0; k < 4; k++) rr[k] = t + 4 * k;

    const float giA = gin[b * 8 + t];
    const float giB = gin[b * 8 + t + 4];

    // ---- H rows t,t+4 packed + H^T scatter; mean ----
    {
        ull hpA[8], hpB[8];
        const float4* H4 = reinterpret_cast<const float4*>(gH + b * 128);
#pragma unroll
        for (int q = 0; q < 4; q++) {
            float4 va = H4[t * 4 + q];
            hpA[2*q] = pk2(va.x, va.y); hpA[2*q+1] = pk2(va.z, va.w);
            S[AXO + (4*q+0)*16 + t] = va.x; S[AXO + (4*q+1)*16 + t] = va.y;
            S[AXO + (4*q+2)*16 + t] = va.z; S[AXO + (4*q+3)*16 + t] = va.w;
            float4 vb = H4[(t + 4) * 4 + q];
            hpB[2*q] = pk2(vb.x, vb.y); hpB[2*q+1] = pk2(vb.z, vb.w);
            S[AXO + (4*q+0)*16 + t+4] = vb.x; S[AXO + (4*q+1)*16 + t+4] = vb.y;
            S[AXO + (4*q+2)*16 + t+4] = vb.z; S[AXO + (4*q+3)*16 + t+4] = vb.w;
        }
#pragma unroll
        for (int k = 0; k < 4; k++) S[ASM + rr[k]] = gmean[b * 16 + rr[k]];
        __syncwarp();

        // ---- resid first: hpA/hpB die here ----
        const float* mp = &S[ASM];
        u2 q0 = *reinterpret_cast<const u2*>(mp);
        u2 q1 = *reinterpret_cast<const u2*>(mp + 4);
        u2 q2 = *reinterpret_cast<const u2*>(mp + 8);
        u2 q3 = *reinterpret_cast<const u2*>(mp + 12);
        ull a0 = ffma2(hpA[0], q0.x, 0ull), a1 = ffma2(hpA[1], q0.y, 0ull);
        a0 = ffma2(hpA[2], q1.x, a0); a1 = ffma2(hpA[3], q1.y, a1);
        a0 = ffma2(hpA[4], q2.x, a0); a1 = ffma2(hpA[5], q2.y, a1);
        a0 = ffma2(hpA[6], q3.x, a0); a1 = ffma2(hpA[7], q3.y, a1);
        S[ASR + t] = giA - hsum(add2(a0, a1));
        ull b0 = ffma2(hpB[0], q0.x, 0ull), b1 = ffma2(hpB[1], q0.y, 0ull);
        b0 = ffma2(hpB[2], q1.x, b0); b1 = ffma2(hpB[3], q1.y, b1);
        b0 = ffma2(hpB[4], q2.x, b0); b1 = ffma2(hpB[5], q2.y, b1);
        b0 = ffma2(hpB[6], q3.x, b0); b1 = ffma2(hpB[7], q3.y, b1);
        S[ASR + t + 4] = giB - hsum(add2(b0, b1));
    }

    // ---- phase 1: PHt rows; cov whole in regs, dies after ----
    ull ph[4][4];
#pragma unroll
    for (int k = 0; k < 4; k++)
#pragma unroll
        for (int p = 0; p < 4; p++) ph[k][p] = 0ull;
    {
        const float4* P4 = reinterpret_cast<const float4*>(gcov + b * 256);
        float c[4][16];
#pragma unroll
        for (int k = 0; k < 4; k++)
#pragma unroll
            for (int q = 0; q < 4; q++) {
                float4 v = P4[rr[k] * 4 + q];
                c[k][4*q] = v.x; c[k][4*q+1] = v.y; c[k][4*q+2] = v.z; c[k][4*q+3] = v.w;
            }
#pragma unroll
        for (int s = 0; s < 16; s++) {
            u2 hA = *reinterpret_cast<const u2*>(&S[AXO + s * 16]);
            u2 hB = *reinterpret_cast<const u2*>(&S[AXO + s * 16 + 4]);
#pragma unroll
            for (int k = 0; k < 4; k++) {
                ull cs = pk1(c[k][s]);
                ph[k][0] = ffma2(hA.x, cs, ph[k][0]); ph[k][1] = ffma2(hA.y, cs, ph[k][1]);
                ph[k][2] = ffma2(hB.x, cs, ph[k][2]); ph[k][3] = ffma2(hB.y, cs, ph[k][3]);
            }
        }
    }
    __syncwarp();   // HT reads done before WT overlays rows 0..7
#pragma unroll
    for (int k = 0; k < 4; k++)
#pragma unroll
        for (int p = 0; p < 4; p++) {
            float lo, hi; upk(ph[k][p], lo, hi);
            S[AWT + (2*p)     * 16 + rr[k]] = lo;
            S[AWT + (2*p + 1) * 16 + rr[k]] = hi;
        }
    __syncwarp();

    // ---- phase 2: re-read H (L1-hot); S rows t,t+4 ----
    {
        const float4* H4 = reinterpret_cast<const float4*>(gH + b * 128);
#pragma unroll
        for (int half = 0; half < 2; half++) {
            const int i = t + 4 * half;
            ull hp[8];
#pragma unroll
            for (int q = 0; q < 4; q++) {
                float4 v = H4[i * 4 + q];
                hp[2*q] = pk2(v.x, v.y); hp[2*q+1] = pk2(v.z, v.w);
            }
            float4 R0 = *reinterpret_cast<const float4*>(gR + b * 64 + i * 8);
            float4 R1 = *reinterpret_cast<const float4*>(gR + b * 64 + i * 8 + 4);
            float rv[8] = {R0.x,R0.y,R0.z,R0.w, R1.x,R1.y,R1.z,R1.w};
            float sv[8];
#pragma unroll
            for (int j = 0; j < 8; j++) {
                const float* wr = &S[AWT + j * 16];
                u2 w0 = *reinterpret_cast<const u2*>(wr);
                u2 w1 = *reinterpret_cast<const u2*>(wr + 4);
                u2 w2 = *reinterpret_cast<const u2*>(wr + 8);
                u2 w3 = *reinterpret_cast<const u2*>(wr + 12);
                ull a0 = ffma2(hp[0], w0.x, 0ull), a1 = ffma2(hp[1], w0.y, 0ull);
                a0 = ffma2(hp[2], w1.x, a0); a1 = ffma2(hp[3], w1.y, a1);
                a0 = ffma2(hp[4], w2.x, a0); a1 = ffma2(hp[5], w2.y, a1);
                a0 = ffma2(hp[6], w3.x, a0); a1 = ffma2(hp[7], w3.y, a1);
                sv[j] = rv[j] + hsum(add2(a0, a1));
            }
            float4* sd = reinterpret_cast<float4*>(&S[ASS + i * 8]);
            sd[0] = make_float4(sv[0], sv[1], sv[2], sv[3]);
            sd[1] = make_float4(sv[4], sv[5], sv[6], sv[7]);
        }
    }
    __syncwarp();

    // ---- Cholesky (redundant per lane); solves read RHS from WT ----
    float L[28], dinv[8];
#pragma unroll
    for (int j = 0; j < 8; j++) {
        float d = S[ASS + j * 8 + j];
#pragma unroll
        for (int k2 = 0; k2 < j; k2++) d -= L[j*(j-1)/2 + k2] * L[j*(j-1)/2 + k2];
        float inv = rsqrtf(d);
        dinv[j] = inv;
#pragma unroll
        for (int i2 = j + 1; i2 < 8; i2++) {
            float e = S[ASS + i2 * 8 + j];
#pragma unroll
            for (int k2 = 0; k2 < j; k2++) e -= L[i2*(i2-1)/2 + k2] * L[j*(j-1)/2 + k2];
            L[i2*(i2-1)/2 + j] = e * inv;
        }
    }
    float K[4][8];
#pragma unroll
    for (int k = 0; k < 4; k++) {
        float y[8];
#pragma unroll
        for (int j = 0; j < 8; j++) {
            float e = S[AWT + j * 16 + rr[k]];
#pragma unroll
            for (int k2 = 0; k2 < j; k2++) e -= L[j*(j-1)/2 + k2] * y[k2];
            y[j] = e * dinv[j];
        }
#pragma unroll
        for (int j = 7; j >= 0; j--) {
            float e = y[j];
#pragma unroll
            for (int k2 = j + 1; k2 < 8; k2++) e -= L[k2*(k2-1)/2 + j] * K[k][k2];
            K[k][j] = e * dinv[j];
        }
    }

    // ---- new_mean -> scratch ----
    if (valid) {
        u2 e0 = *reinterpret_cast<const u2*>(&S[ASR]);
        u2 e1 = *reinterpret_cast<const u2*>(&S[ASR + 4]);
#pragma unroll
        for (int k = 0; k < 4; k++) {
            ull a0 = ffma2(pk2(K[k][0], K[k][1]), e0.x, 0ull);
            ull a1 = ffma2(pk2(K[k][2], K[k][3]), e0.y, 0ull);
            a0 = ffma2(pk2(K[k][4], K[k][5]), e1.x, a0);
            a1 = ffma2(pk2(K[k][6], K[k][7]), e1.y, a1);
            g_nm[b * 16 + rr[k]] = S[ASM + rr[k]] + hsum(add2(a0, a1));
        }
    }

    // ---- phase 6: NC = cov - K.W -> scratch ----
    ull nc[4][8];
    {
        const float4* P4 = reinterpret_cast<const float4*>(gcov + b * 256);
#pragma unroll
        for (int k = 0; k < 4; k++)
#pragma unroll
            for (int q = 0; q < 4; q++) {
                float4 v = P4[rr[k] * 4 + q];
                nc[k][2*q] = pk2(v.x, v.y); nc[k][2*q+1] = pk2(v.z, v.w);
            }
    }
#pragma unroll
    for (int o = 0; o < 8; o++) {
        const float* wr = &S[AWT + o * 16];
        u2 w0 = *reinterpret_cast<const u2*>(wr);
        u2 w1 = *reinterpret_cast<const u2*>(wr + 4);
        u2 w2 = *reinterpret_cast<const u2*>(wr + 8);
        u2 w3 = *reinterpret_cast<const u2*>(wr + 12);
#pragma unroll
        for (int k = 0; k < 4; k++) {
            ull nk = pk1(-K[k][o]);
            nc[k][0] = ffma2(w0.x, nk, nc[k][0]); nc[k][1] = ffma2(w0.y, nk, nc[k][1]);
            nc[k][2] = ffma2(w1.x, nk, nc[k][2]); nc[k][3] = ffma2(w1.y, nk, nc[k][3]);
            nc[k][4] = ffma2(w2.x, nk, nc[k][4]); nc[k][5] = ffma2(w2.y, nk, nc[k][5]);
            nc[k][6] = ffma2(w3.x, nk, nc[k][6]); nc[k][7] = ffma2(w3.y, nk, nc[k][7]);
        }
    }
    if (valid) {
#pragma unroll
        for (int k = 0; k < 4; k++) {
            float v[16];
#pragma unroll
            for (int p = 0; p < 8; p++) upk(nc[k][p], v[2*p], v[2*p+1]);
            float4* od = reinterpret_cast<float4*>(g_nc + b * 256 + rr[k] * 16);
            od[0] = make_float4(v[0],  v[1],  v[2],  v[3]);
            od[1] = make_float4(v[4],  v[5],  v[6],  v[7]);
            od[2] = make_float4(v[8],  v[9],  v[10], v[11]);
            od[3] = make_float4(v[12], v[13], v[14], v[15]);
        }
    }
}

// ============================ Kernel B: predict ===========================
static constexpr int GBB = 16;       // batches per block
static constexpr int TPB = 128;      // 8 lanes per batch
static constexpr int BSB   = 276;    // ≡20 mod 32: 4 warp-groups on disjoint quads
static constexpr int BXO   = 0;      // 16x16: NC -> F rows (as F^T)
static constexpr int BNM   = 256;

__global__ void __launch_bounds__(TPB, 4) kf_predict(
    const float* __restrict__ gF, const float* __restrict__ gQ,
    float* __restrict__ omean, float* __restrict__ ocov, int nb)
{
    __shared__ __align__(16) float sm[GBB * BSB];
    const int g = threadIdx.x >> 3;
    const int t = threadIdx.x & 7;
    long long b = (long long)blockIdx.x * GBB + g;
    const bool valid = (b < nb);
    if (!valid) b = nb - 1;
    float* S = sm + g * BSB;
    const int ro = (t >> 1) & 3;     // chunk rotation vs 16t bank aliasing

    // ---- NC rows t, t+8 from scratch -> X (u2 stores, rotated) ----
    {
        const u2* ncg = reinterpret_cast<const u2*>(g_nc + b * 256);
#pragma unroll
        for (int half = 0; half < 2; half++) {
            const int row = t + 8 * half;
            u2 r0 = ncg[row * 4 + 0], r1 = ncg[row * 4 + 1];
            u2 r2 = ncg[row * 4 + 2], r3 = ncg[row * 4 + 3];
            u2 rv[4] = {r0, r1, r2, r3};
            u2* xr = reinterpret_cast<u2*>(&S[BXO + row * 16]);
#pragma unroll
            for (int j = 0; j < 4; j++) {
                int cj = (j + ro) & 3;
                xr[cj] = rv[cj];
            }
        }
    }
    S[BNM + t]     = g_nm[b * 16 + t];
    S[BNM + t + 8] = g_nm[b * 16 + t + 8];
    __syncwarp();

    // ---- F rows t, t+8 -> regs; pred_mean ----
    float f0[16], f1[16];
    {
        const float4* F4 = reinterpret_cast<const float4*>(gF + b * 256);
#pragma unroll
        for (int q = 0; q < 4; q++) {
            float4 v = F4[t * 4 + q];
            f0[4*q] = v.x; f0[4*q+1] = v.y; f0[4*q+2] = v.z; f0[4*q+3] = v.w;
            float4 w = F4[(t + 8) * 4 + q];
            f1[4*q] = w.x; f1[4*q+1] = w.y; f1[4*q+2] = w.z; f1[4*q+3] = w.w;
        }
    }
    {
        const float* np = &S[BNM];
        u2 n0 = *reinterpret_cast<const u2*>(np);
        u2 n1 = *reinterpret_cast<const u2*>(np + 4);
        u2 n2 = *reinterpret_cast<const u2*>(np + 8);
        u2 n3 = *reinterpret_cast<const u2*>(np + 12);
        ull a0 = ffma2(pk2(f0[0],  f0[1]),  n0.x, 0ull);
        ull a1 = ffma2(pk2(f0[2],  f0[3]),  n0.y, 0ull);
        a0 = ffma2(pk2(f0[4],  f0[5]),  n1.x, a0);
        a1 = ffma2(pk2(f0[6],  f0[7]),  n1.y, a1);
        a0 = ffma2(pk2(f0[8],  f0[9]),  n2.x, a0);
        a1 = ffma2(pk2(f0[10], f0[11]), n2.y, a1);
        a0 = ffma2(pk2(f0[12], f0[13]), n3.x, a0);
        a1 = ffma2(pk2(f0[14], f0[15]), n3.y, a1);
        ull b0 = ffma2(pk2(f1[0],  f1[1]),  n0.x, 0ull);
        ull b1 = ffma2(pk2(f1[2],  f1[3]),  n0.y, 0ull);
        b0 = ffma2(pk2(f1[4],  f1[5]),  n1.x, b0);
        b1 = ffma2(pk2(f1[6],  f1[7]),  n1.y, b1);
        b0 = ffma2(pk2(f1[8],  f1[9]),  n2.x, b0);
        b1 = ffma2(pk2(f1[10], f1[11]), n2.y, b1);
        b0 = ffma2(pk2(f1[12], f1[13]), n3.x, b0);
        b1 = ffma2(pk2(f1[14], f1[15]), n3.y, b1);
        if (valid) {
            omean[b * 16 + t]     = hsum(add2(a0, a1));
            omean[b * 16 + t + 8] = hsum(add2(b0, b1));
        }
    }

    // ---- phase 7: tm rows t,t+8 (packed in tp0/tp1) = F row . NC ----
    ull tp0[8], tp1[8];
#pragma unroll
    for (int p = 0; p < 8; p++) { tp0[p] = 0ull; tp1[p] = 0ull; }
#pragma unroll
    for (int u = 0; u < 16; u++) {
        const float* nr = &S[BXO + u * 16];
        u2 n0 = *reinterpret_cast<const u2*>(nr);
        u2 n1 = *reinterpret_cast<const u2*>(nr + 4);
        u2 n2 = *reinterpret_cast<const u2*>(nr + 8);
        u2 n3 = *reinterpret_cast<const u2*>(nr + 12);
        ull fu0 = pk1(f0[u]), fu1 = pk1(f1[u]);
        tp0[0] = ffma2(n0.x, fu0, tp0[0]); tp0[1] = ffma2(n0.y, fu0, tp0[1]);
        tp0[2] = ffma2(n1.x, fu0, tp0[2]); tp0[3] = ffma2(n1.y, fu0, tp0[3]);
        tp0[4] = ffma2(n2.x, fu0, tp0[4]); tp0[5] = ffma2(n2.y, fu0, tp0[5]);
        tp0[6] = ffma2(n3.x, fu0, tp0[6]); tp0[7] = ffma2(n3.y, fu0, tp0[7]);
        tp1[0] = ffma2(n0.x, fu1, tp1[0]); tp1[1] = ffma2(n0.y, fu1, tp1[1]);
        tp1[2] = ffma2(n1.x, fu1, tp1[2]); tp1[3] = ffma2(n1.y, fu1, tp1[3]);
        tp1[4] = ffma2(n2.x, fu1, tp1[4]); tp1[5] = ffma2(n2.y, fu1, tp1[5]);
        tp1[6] = ffma2(n3.x, fu1, tp1[6]); tp1[7] = ffma2(n3.y, fu1, tp1[7]);
    }
    __syncwarp();   // NC reads done before F^T overlays X

    // ---- F^T into X (f dies) ----
#pragma unroll
    for (int u = 0; u < 16; u++) {
        S[BXO + u * 16 + t]     = f0[u];
        S[BXO + u * 16 + t + 8] = f1[u];
    }
    __syncwarp();

    // ---- phase 8: pc = Q + sum_u tm[u] * F^T[u][:]; tm unpacked from tp ----
    ull pc0[8], pc1[8];
    {
        const float4* Q4 = reinterpret_cast<const float4*>(gQ + b * 256);
#pragma unroll
        for (int q = 0; q < 4; q++) {
            float4 v = Q4[t * 4 + q];
            pc0[2*q] = pk2(v.x, v.y); pc0[2*q+1] = pk2(v.z, v.w);
            float4 w = Q4[(t + 8) * 4 + q];
            pc1[2*q] = pk2(w.x, w.y); pc1[2*q+1] = pk2(w.z, w.w);
        }
    }
#pragma unroll
    for (int p = 0; p < 8; p++) {
#pragma unroll
        for (int half = 0; half < 2; half++) {
            const int u = 2 * p + half;
            const float* fr = &S[BXO + u * 16];
            u2 e0 = *reinterpret_cast<const u2*>(fr);
            u2 e1 = *reinterpret_cast<const u2*>(fr + 4);
            u2 e2 = *reinterpret_cast<const u2*>(fr + 8);
            u2 e3 = *reinterpret_cast<const u2*>(fr + 12);
            float l0, h0, l1, h1;
            upk(tp0[p], l0, h0); upk(tp1[p], l1, h1);
            ull tu0 = pk1(half ? h0 : l0);
            ull tu1 = pk1(half ? h1 : l1);
            pc0[0] = ffma2(e0.x, tu0, pc0[0]); pc0[1] = ffma2(e0.y, tu0, pc0[1]);
            pc0[2] = ffma2(e1.x, tu0, pc0[2]); pc0[3] = ffma2(e1.y, tu0, pc0[3]);
            pc0[4] = ffma2(e2.x, tu0, pc0[4]); pc0[5] = ffma2(e2.y, tu0, pc0[5]);
            pc0[6] = ffma2(e3.x, tu0, pc0[6]); pc0[7] = ffma2(e3.y, tu0, pc0[7]);
            pc1[0] = ffma2(e0.x, tu1, pc1[0]); pc1[1] = ffma2(e0.y, tu1, pc1[1]);
            pc1[2] = ffma2(e1.x, tu1, pc1[2]); pc1[3] = ffma2(e1.y, tu1, pc1[3]);
            pc1[4] = ffma2(e2.x, tu1, pc1[4]); pc1[5] = ffma2(e2.y, tu1, pc1[5]);
            pc1[6] = ffma2(e3.x, tu1, pc1[6]); pc1[7] = ffma2(e3.y, tu1, pc1[7]);
        }
    }

    if (valid) {
        float v[16];
        float4* od0 = reinterpret_cast<float4*>(ocov + b * 256 + t * 16);
#pragma unroll
        for (int p = 0; p < 8; p++) upk(pc0[p], v[2*p], v[2*p+1]);
        od0[0] = make_float4(v[0],  v[1],  v[2],  v[3]);
        od0[1] = make_float4(v[4],  v[5],  v[6],  v[7]);
        od0[2] = make_float4(v[8],  v[9],  v[10], v[11]);
        od0[3] = make_float4(v[12], v[13], v[14], v[15]);
        float4* od1 = reinterpret_cast<float4*>(ocov + b * 256 + (t + 8) * 16);
#pragma unroll
        for (int p = 0; p < 8; p++) upk(pc1[p], v[2*p], v[2*p+1]);
        od1[0] = make_float4(v[0],  v[1],  v[2],  v[3]);
        od1[1] = make_float4(v[4],  v[5],  v[6],  v[7]);
        od1[2] = make_float4(v[8],  v[9],  v[10], v[11]);
        od1[3] = make_float4(v[12], v[13], v[14], v[15]);
    }
}

extern "C" void kernel_launch(void* const* d_in, const int* in_sizes, int n_in,
                              void* d_out, int out_size)
{
    const float* gin   = (const float*)d_in[0];
    const float* gmean = (const float*)d_in[1];
    const float* gcov  = (const float*)d_in[2];
    const float* gH    = (const float*)d_in[3];
    const float* gR    = (const float*)d_in[4];
    const float* gF    = (const float*)d_in[5];
    const float* gQ    = (const float*)d_in[6];

    const int nb = in_sizes[1] / 16;
    float* omean = (float*)d_out;
    float* ocov  = omean + (size_t)nb * 16;

    const int blkA = (nb + GA - 1) / GA;
    kf_update<<<blkA, TPA>>>(gin, gmean, gcov, gH, gR, nb);
    const int blkB = (nb + GBB - 1) / GBB;
    kf_predict<<<blkB, TPB>>>(gF, gQ, omean, ocov, nb);
}